// round 17
// baseline (speedup 1.0000x reference)
#include <cuda_runtime.h>
#include <cuda_bf16.h>
#include <cstdint>

#define NB 256
#define NS 512
#define ND 256
#define NA 128
#define TS 128
#define NTILE (NS / TS)     // 4
#define KC 32
#define NCHUNK (ND / KC)    // 8
#define ASTR 40             // bf16 row stride (elems) = 80B, ldmatrix conflict-free

// ---- scratch (allocation-free rule: device globals) ----
__device__ float g_part[NB * NTILE * ND];
__device__ float g_esum[NB * NTILE];
__device__ __nv_bfloat16 g_wt_hi[NA * ND];   // [n][k] K-major
__device__ __nv_bfloat16 g_wt_lo[NA * ND];

// ---- smem layout (bytes), identical to round 4/15/16 ----
#define H_ES    0
#define H_BSM   512
#define H_USM   1024
#define H_RED   1536
#define H_TILES 2048
#define HTILE_B (TS * ASTR * 2)          // 10240
#define H_AH(buf) (H_TILES + (buf) * 4 * HTILE_B + 0 * HTILE_B)
#define H_AL(buf) (H_TILES + (buf) * 4 * HTILE_B + 1 * HTILE_B)
#define H_BH(buf) (H_TILES + (buf) * 4 * HTILE_B + 2 * HTILE_B)
#define H_BL(buf) (H_TILES + (buf) * 4 * HTILE_B + 3 * HTILE_B)
#define SMEM_TOTAL (H_TILES + 8 * HTILE_B)   // 83968

#define LDSM4(r, addr) \
    asm volatile("ldmatrix.sync.aligned.m8n8.x4.shared.b16 {%0,%1,%2,%3}, [%4];" \
        : "=r"((r)[0]), "=r"((r)[1]), "=r"((r)[2]), "=r"((r)[3]) : "r"(addr))

#define MMA16816(d, a, b0, b1) \
    asm volatile("mma.sync.aligned.m16n8k16.row.col.f32.bf16.bf16.f32 " \
        "{%0,%1,%2,%3},{%4,%5,%6,%7},{%8,%9},{%0,%1,%2,%3};" \
        : "+f"((d)[0]), "+f"((d)[1]), "+f"((d)[2]), "+f"((d)[3]) \
        : "r"((a)[0]), "r"((a)[1]), "r"((a)[2]), "r"((a)[3]), "r"(b0), "r"(b1))

__device__ __forceinline__ void cp16(char* dst, const char* src) {
    unsigned saddr = (unsigned)__cvta_generic_to_shared(dst);
    asm volatile("cp.async.cg.shared.global [%0], [%1], 16;\n" :: "r"(saddr), "l"(src));
}
__device__ __forceinline__ void cp_commit() { asm volatile("cp.async.commit_group;\n"); }
template<int N> __device__ __forceinline__ void cp_wait() {
    asm volatile("cp.async.wait_group %0;\n" :: "n"(N));
}
__device__ __forceinline__ uint32_t pack_bf2(float a, float b) {
    __nv_bfloat162 t = __halves2bfloat162(__float2bfloat16(a), __float2bfloat16(b));
    return *(uint32_t*)&t;
}
__device__ __forceinline__ float fast_tanh(float x) {
    float e = __expf(2.0f * x);
    return 1.0f - __fdividef(2.0f, e + 1.0f);
}

// ---------------------------------------------------------------------------
// wprep: coalesced stores.  Thread handles one (n, k-pair): reads W[2k][n],
// W[2k+1][n], writes one bf16x2 word at [n][k] -> consecutive threads write
// consecutive words.
// ---------------------------------------------------------------------------
__global__ void __launch_bounds__(256) wprep_kernel(const float* __restrict__ W) {
    int idx = blockIdx.x * 256 + threadIdx.x;        // over 128n * 128 k-pairs
    if (idx < NA * (ND / 2)) {
        int n  = idx >> 7;            // 0..127
        int k2 = idx & 127;           // k-pair index
        float w0 = __ldg(&W[(size_t)(2 * k2)     * NA + n]);
        float w1 = __ldg(&W[(size_t)(2 * k2 + 1) * NA + n]);
        __nv_bfloat16 h0 = __float2bfloat16(w0);
        __nv_bfloat16 h1 = __float2bfloat16(w1);
        float l0 = w0 - __bfloat162float(h0);
        float l1 = w1 - __bfloat162float(h1);
        __nv_bfloat162 hp = __halves2bfloat162(h0, h1);
        __nv_bfloat162 lp = __halves2bfloat162(__float2bfloat16(l0), __float2bfloat16(l1));
        ((uint32_t*)g_wt_hi)[n * (ND / 2) + k2] = *(uint32_t*)&hp;   // coalesced
        ((uint32_t*)g_wt_lo)[n * (ND / 2) + k2] = *(uint32_t*)&lp;
    }
#if __CUDA_ARCH__ >= 900
    cudaTriggerProgrammaticLaunchCompletion();
#endif
}

// ---------------------------------------------------------------------------
// Round-4/15/16 engine (byte-identical mainloop) + PDL.
// ---------------------------------------------------------------------------
__global__ void __launch_bounds__(256, 2) scores_kernel(
    const float* __restrict__ x, const float* __restrict__ bias,
    const float* __restrict__ u)
{
    extern __shared__ char smem[];
    const uint32_t smb = (uint32_t)__cvta_generic_to_shared(smem);

    const int b    = blockIdx.y;
    const int tile = blockIdx.x;
    const int s0   = tile * TS;
    const int tid  = threadIdx.x;
    const int w    = tid >> 5;
    const int l    = tid & 31;
    const int wm   = w >> 1;       // rows wm*32
    const int wn   = w & 1;        // cols wn*64

    float* es  = (float*)(smem + H_ES);
    float* bsm = (float*)(smem + H_BSM);
    float* usm = (float*)(smem + H_USM);
    float* red = (float*)(smem + H_RED);

    if (tid < NA) { bsm[tid] = bias[tid]; usm[tid] = u[tid]; }
    if (tid < TS) red[tid] = 0.0f;

    const float* xb = x + ((size_t)b * NS + s0) * ND;

    const int xrow = tid >> 1, xcolh = tid & 1;
    float4 st[4];
    auto load_x = [&](int c) {
        const float* p = xb + (size_t)xrow * ND + c * KC + xcolh * 16;
#pragma unroll
        for (int i = 0; i < 4; i++) st[i] = ((const float4*)p)[i];
    };
    auto sts_x = [&](int buf) {
        uint32_t hv[8], lv[8];
#pragma unroll
        for (int i = 0; i < 4; i++) {
            float vs[4] = { st[i].x, st[i].y, st[i].z, st[i].w };
            float ls[4];
#pragma unroll
            for (int j = 0; j < 4; j++) {
                __nv_bfloat16 h = __float2bfloat16(vs[j]);
                ls[j] = vs[j] - __bfloat162float(h);
            }
            hv[2*i]   = pack_bf2(vs[0], vs[1]);
            hv[2*i+1] = pack_bf2(vs[2], vs[3]);
            lv[2*i]   = pack_bf2(ls[0], ls[1]);
            lv[2*i+1] = pack_bf2(ls[2], ls[3]);
        }
        int off = xrow * (ASTR * 2) + xcolh * 32;
        *(uint4*)(smem + H_AH(buf) + off)      = make_uint4(hv[0], hv[1], hv[2], hv[3]);
        *(uint4*)(smem + H_AH(buf) + off + 16) = make_uint4(hv[4], hv[5], hv[6], hv[7]);
        *(uint4*)(smem + H_AL(buf) + off)      = make_uint4(lv[0], lv[1], lv[2], lv[3]);
        *(uint4*)(smem + H_AL(buf) + off + 16) = make_uint4(lv[4], lv[5], lv[6], lv[7]);
    };
    auto cp_w = [&](int c, int buf) {
#pragma unroll
        for (int it = 0; it < 4; it++) {
            int idx = tid + it * 256;
            int h = idx >> 9, rem = idx & 511;
            int n = rem >> 2, s = rem & 3;
            const char* src = (const char*)(h ? g_wt_lo : g_wt_hi) + (size_t)n * (ND * 2) + c * (KC * 2) + s * 16;
            cp16(smem + (h ? H_BL(buf) : H_BH(buf)) + n * (ASTR * 2) + s * 16, src);
        }
        cp_commit();
    };

    float acc[2][8][4];
#pragma unroll
    for (int m = 0; m < 2; m++)
#pragma unroll
        for (int nf = 0; nf < 8; nf++)
#pragma unroll
            for (int e = 0; e < 4; e++) acc[m][nf][e] = 0.0f;

    const uint32_t lane_off = (uint32_t)((l & 15) * (ASTR * 2) + (l >> 4) * 16);

    // ---- prologue: W-independent work first, then wait for wprep ----
    load_x(0);
#if __CUDA_ARCH__ >= 900
    cudaGridDependencySynchronize();     // g_wt_hi/lo ready past this point
#endif
    cp_w(0, 0);
    sts_x(0);

#pragma unroll 1
    for (int c = 0; c < NCHUNK; c++) {
        const int buf = c & 1;
        cp_wait<0>();
        __syncthreads();
        if (c < NCHUNK - 1) {
            cp_w(c + 1, buf ^ 1);
            load_x(c + 1);
        }

        const uint32_t ah_base = smb + H_AH(buf) + (uint32_t)(wm * 32) * (ASTR * 2) + lane_off;
        const uint32_t al_base = smb + H_AL(buf) + (uint32_t)(wm * 32) * (ASTR * 2) + lane_off;
        const uint32_t bh_base = smb + H_BH(buf) + (uint32_t)(wn * 64) * (ASTR * 2) + lane_off;
        const uint32_t bl_base = smb + H_BL(buf) + (uint32_t)(wn * 64) * (ASTR * 2) + lane_off;

#pragma unroll
        for (int kk = 0; kk < KC; kk += 16) {
            uint32_t ah[2][4], al[2][4];
#pragma unroll
            for (int m = 0; m < 2; m++) {
                LDSM4(ah[m], ah_base + m * 16 * (ASTR * 2) + kk * 2);
                LDSM4(al[m], al_base + m * 16 * (ASTR * 2) + kk * 2);
            }
#pragma unroll
            for (int np = 0; np < 4; np++) {
                uint32_t bh[4], bl[4];
                LDSM4(bh, bh_base + np * 16 * (ASTR * 2) + kk * 2);
                LDSM4(bl, bl_base + np * 16 * (ASTR * 2) + kk * 2);
#pragma unroll
                for (int m = 0; m < 2; m++)
#pragma unroll
                    for (int sn = 0; sn < 2; sn++) {
                        float* d = acc[m][np * 2 + sn];
                        uint32_t h0 = sn ? bh[1] : bh[0], h1 = sn ? bh[3] : bh[2];
                        uint32_t l0 = sn ? bl[1] : bl[0], l1 = sn ? bl[3] : bl[2];
                        MMA16816(d, ah[m], h0, h1);
                        MMA16816(d, ah[m], l0, l1);
                        MMA16816(d, al[m], h0, h1);
                    }
            }
        }
        if (c < NCHUNK - 1) sts_x(buf ^ 1);
    }

    // ---- epilogue ----
    __syncthreads();
    const int g = l >> 2, tig = l & 3;
#pragma unroll
    for (int m = 0; m < 2; m++) {
        float pA = 0.0f, pB = 0.0f;
#pragma unroll
        for (int nf = 0; nf < 8; nf++)
#pragma unroll
            for (int e = 0; e < 2; e++) {
                int col = wn * 64 + nf * 8 + 2 * tig + e;
                pA += fast_tanh(acc[m][nf][e]     + bsm[col]) * usm[col];
                pB += fast_tanh(acc[m][nf][2 + e] + bsm[col]) * usm[col];
            }
        pA += __shfl_xor_sync(0xffffffffu, pA, 1);
        pA += __shfl_xor_sync(0xffffffffu, pA, 2);
        pB += __shfl_xor_sync(0xffffffffu, pB, 1);
        pB += __shfl_xor_sync(0xffffffffu, pB, 2);
        if (tig == 0) {
            int row = wm * 32 + m * 16 + g;
            atomicAdd(&red[row], pA);          // exactly 2 contributors/row
            atomicAdd(&red[row + 8], pB);
        }
    }
    __syncthreads();
    if (tid < TS) es[tid] = expf(red[tid]);    // faithful: no max-subtraction
    __syncthreads();

    if (tid < 64) red[tid] = es[tid] + es[tid + 64];
    __syncthreads();
    if (tid < 32) {
        float v = red[tid] + red[tid + 32];
#pragma unroll
        for (int off = 16; off > 0; off >>= 1)
            v += __shfl_down_sync(0xffffffffu, v, off);
        if (tid == 0) g_esum[b * NTILE + tile] = v;
    }

    float a0 = 0.f, a1 = 0.f, a2 = 0.f, a3 = 0.f;
#pragma unroll 4
    for (int s = 0; s < TS; s += 4) {
        a0 += es[s + 0] * xb[(size_t)(s + 0) * ND + tid];
        a1 += es[s + 1] * xb[(size_t)(s + 1) * ND + tid];
        a2 += es[s + 2] * xb[(size_t)(s + 2) * ND + tid];
        a3 += es[s + 3] * xb[(size_t)(s + 3) * ND + tid];
    }
    g_part[((size_t)b * NTILE + tile) * ND + tid] = (a0 + a1) + (a2 + a3);

#if __CUDA_ARCH__ >= 900
    cudaTriggerProgrammaticLaunchCompletion();
#endif
}

// ---------------------------------------------------------------------------
__global__ void __launch_bounds__(256) finish_kernel(float* __restrict__ out)
{
#if __CUDA_ARCH__ >= 900
    cudaGridDependencySynchronize();    // all scores blocks complete
#endif
    const int b = blockIdx.x;
    const int tid = threadIdx.x;
    float s = 0.f;
#pragma unroll
    for (int t = 0; t < NTILE; t++) s += g_esum[b * NTILE + t];
    const float inv = 1.0f / (s + 1e-8f);
    float v = 0.f;
#pragma unroll
    for (int t = 0; t < NTILE; t++) v += g_part[((size_t)b * NTILE + t) * ND + tid];
    out[b * ND + tid] = v * inv;
#if __CUDA_ARCH__ >= 900
    // lets next replay's wprep launch during this kernel's tail; executed
    // after the gridsync above, so scores' g_wt reads are already complete.
    cudaTriggerProgrammaticLaunchCompletion();
#endif
}

extern "C" void kernel_launch(void* const* d_in, const int* in_sizes, int n_in,
                              void* d_out, int out_size) {
    const float* x    = (const float*)d_in[0];
    const float* W    = (const float*)d_in[1];
    const float* bias = (const float*)d_in[2];
    const float* u    = (const float*)d_in[3];
    float* out        = (float*)d_out;

    cudaFuncSetAttribute(scores_kernel, cudaFuncAttributeMaxDynamicSharedMemorySize, SMEM_TOTAL);

    cudaLaunchAttribute pdl[1];
    pdl[0].id = cudaLaunchAttributeProgrammaticStreamSerialization;
    pdl[0].val.programmaticStreamSerializationAllowed = 1;

    cudaLaunchConfig_t cfg0 = {};
    cfg0.gridDim = dim3((NA * (ND / 2) + 255) / 256);   // 64 blocks
    cfg0.blockDim = dim3(256);
    cfg0.stream = 0;
    cfg0.attrs = pdl;
    cfg0.numAttrs = 1;
    cudaLaunchKernelEx(&cfg0, wprep_kernel, W);

    cudaLaunchConfig_t cfg1 = {};
    cfg1.gridDim = dim3(NTILE, NB);
    cfg1.blockDim = dim3(256);
    cfg1.dynamicSmemBytes = SMEM_TOTAL;
    cfg1.stream = 0;
    cfg1.attrs = pdl;
    cfg1.numAttrs = 1;
    cudaLaunchKernelEx(&cfg1, scores_kernel, x, bias, u);

    cudaLaunchConfig_t cfg2 = {};
    cfg2.gridDim = dim3(NB);
    cfg2.blockDim = dim3(256);
    cfg2.stream = 0;
    cfg2.attrs = pdl;
    cfg2.numAttrs = 1;
    cudaLaunchKernelEx(&cfg2, finish_kernel, out);
}